// round 3
// baseline (speedup 1.0000x reference)
#include <cuda_runtime.h>
#include <cstdint>

// ---------------- problem constants ----------------
#define BATCH   8
#define SEQ     16384
#define CH      128
#define WIN     32
#define STRD    16
#define NB      1023                 // (16384-32)/16 + 1
#define MROWS   (BATCH*NB)           // 8184
#define K1      4096                 // WIN*CH
#define N1      256
#define K2      256
#define N2      128

// ---------------- scratch (__device__ globals; no allocation) ----------------
__device__ float g_b1p[N1];
__device__ float g_partial[32 * N1];
__device__ float g_h[(size_t)MROWS * N1];   // 8.4 MB intermediate

// ---------------- ptx helpers ----------------
__device__ __forceinline__ uint32_t cvt_tf32(float x) {
    uint32_t u; asm("cvt.rna.tf32.f32 %0, %1;" : "=r"(u) : "f"(x)); return u;
}
__device__ __forceinline__ void mma_tf32(float c[4], const uint32_t a[4], const uint32_t b[2]) {
    asm volatile(
        "mma.sync.aligned.m16n8k8.row.col.f32.tf32.tf32.f32 "
        "{%0,%1,%2,%3}, {%4,%5,%6,%7}, {%8,%9}, {%0,%1,%2,%3};"
        : "+f"(c[0]), "+f"(c[1]), "+f"(c[2]), "+f"(c[3])
        : "r"(a[0]), "r"(a[1]), "r"(a[2]), "r"(a[3]), "r"(b[0]), "r"(b[1]));
}
__device__ __forceinline__ void cp_async16(uint32_t dst, const void* src) {
    asm volatile("cp.async.cg.shared.global [%0], [%1], 16;" :: "r"(dst), "l"(src));
}
__device__ __forceinline__ void cp_commit() {
    asm volatile("cp.async.commit_group;");
}

__device__ __forceinline__ float gelu_exact(float v) {
    return 0.5f * v * (1.0f + erff(v * 0.70710678118654752f));
}

// ---------------- pre-kernels: b1' = b1 + pos_flat @ W1 ----------------
__global__ void pos_w1_partial(const float* __restrict__ pos, const float* __restrict__ W1) {
    int kc = blockIdx.x;            // 0..31, chunk of 128 k-values
    int n  = threadIdx.x;           // 0..255
    int k0 = kc * 128;
    float s = 0.f;
    #pragma unroll 4
    for (int k = 0; k < 128; k++)
        s += pos[k0 + k] * W1[(size_t)(k0 + k) * N1 + n];
    g_partial[kc * N1 + n] = s;
}
__global__ void pos_w1_reduce(const float* __restrict__ b1) {
    int n = threadIdx.x;
    float s = b1[n];
    #pragma unroll
    for (int i = 0; i < 32; i++) s += g_partial[i * N1 + n];
    g_b1p[n] = s;
}

// ---------------- GEMM tile config (shared by both GEMMs) ----------------
#define BM      128
#define BN      128
#define BK      32
#define ASTR    36      // 36 mod 32 = 4  -> conflict-free A fragment LDS
#define BSTR    136     // 136 mod 32 = 8 -> conflict-free B fragment LDS
#define STAGES  3
#define A_ELE   (BM*ASTR)     // 4608 floats
#define B_ELE   (BK*BSTR)     // 4352 floats
#define SMEM_BYTES (STAGES*(A_ELE+B_ELE)*4)   // 107520

// ============ kernel 1: h = gelu(gather(x) @ W1 + b1') ============
__global__ __launch_bounds__(256, 1)
void k1_gemm_gelu(const float* __restrict__ x, const float* __restrict__ W1) {
    extern __shared__ float smem[];
    float* Abuf = smem;
    float* Bbuf = smem + STAGES * A_ELE;

    const int tid   = threadIdx.x;
    const int lane  = tid & 31;
    const int warp  = tid >> 5;
    const int warpM = warp & 3;       // 0..3
    const int warpN = warp >> 2;      // 0..1
    const int qr    = lane >> 2;      // 0..7
    const int qc    = lane & 3;       // 0..3
    const int mtile = blockIdx.x;     // 0..63
    const int ntile = blockIdx.y;     // 0..1

    // A-loader indices (gather): thread loads 4 rows x one float4
    const int arow  = tid >> 3;       // 0..31
    const int acol4 = tid & 7;        // 0..7
    int tokbase[4];
    #pragma unroll
    for (int i = 0; i < 4; i++) {
        int m  = mtile * BM + arow + i * 32;
        int mc = (m < MROWS) ? m : (MROWS - 1);      // safe clamp (stores predicated)
        int b  = mc / NB;
        int blk = mc - b * NB;
        tokbase[i] = b * SEQ + blk * STRD;
    }
    // B-loader indices
    const int bkrow = tid >> 5;       // 0..7
    const int bcol4 = tid & 31;       // 0..31

    const int NCHUNK = K1 / BK;       // 128

    auto load_chunk = [&](int kc) {
        int s   = kc % STAGES;
        int t   = kc >> 2;            // token within window (BK=32, CH=128 -> 4 chunks/token)
        int ch0 = (kc & 3) * 32;
        float* As = Abuf + s * A_ELE;
        float* Bs = Bbuf + s * B_ELE;
        #pragma unroll
        for (int i = 0; i < 4; i++) {
            const float* src = x + (size_t)(tokbase[i] + t) * CH + ch0 + acol4 * 4;
            uint32_t dst = (uint32_t)__cvta_generic_to_shared(As + (arow + i * 32) * ASTR + acol4 * 4);
            cp_async16(dst, src);
        }
        #pragma unroll
        for (int i = 0; i < 4; i++) {
            int kr = bkrow + i * 8;
            const float* src = W1 + (size_t)(kc * BK + kr) * N1 + ntile * BN + bcol4 * 4;
            uint32_t dst = (uint32_t)__cvta_generic_to_shared(Bs + kr * BSTR + bcol4 * 4);
            cp_async16(dst, src);
        }
    };

    float acc[2][8][4];
    #pragma unroll
    for (int a = 0; a < 2; a++)
        #pragma unroll
        for (int b = 0; b < 8; b++)
            #pragma unroll
            for (int c = 0; c < 4; c++) acc[a][b][c] = 0.f;

    #pragma unroll
    for (int c = 0; c < STAGES - 1; c++) { load_chunk(c); cp_commit(); }

    for (int kc = 0; kc < NCHUNK; kc++) {
        asm volatile("cp.async.wait_group %0;" :: "n"(STAGES - 2));
        __syncthreads();
        if (kc + STAGES - 1 < NCHUNK) load_chunk(kc + STAGES - 1);
        cp_commit();

        int s = kc % STAGES;
        const float* As = Abuf + s * A_ELE;
        const float* Bs = Bbuf + s * B_ELE;
        #pragma unroll
        for (int ks = 0; ks < 4; ks++) {
            uint32_t af[2][4];
            #pragma unroll
            for (int mi = 0; mi < 2; mi++) {
                int r0 = warpM * 32 + mi * 16 + qr;
                af[mi][0] = cvt_tf32(As[ r0      * ASTR + ks * 8 + qc    ]);
                af[mi][1] = cvt_tf32(As[(r0 + 8) * ASTR + ks * 8 + qc    ]);
                af[mi][2] = cvt_tf32(As[ r0      * ASTR + ks * 8 + qc + 4]);
                af[mi][3] = cvt_tf32(As[(r0 + 8) * ASTR + ks * 8 + qc + 4]);
            }
            #pragma unroll
            for (int ni = 0; ni < 8; ni++) {
                int c0 = warpN * 64 + ni * 8 + qr;
                uint32_t bf[2];
                bf[0] = cvt_tf32(Bs[(ks * 8 + qc    ) * BSTR + c0]);
                bf[1] = cvt_tf32(Bs[(ks * 8 + qc + 4) * BSTR + c0]);
                mma_tf32(acc[0][ni], af[0], bf);
                mma_tf32(acc[1][ni], af[1], bf);
            }
        }
    }

    // epilogue: bias + exact GELU -> g_h
    #pragma unroll
    for (int ni = 0; ni < 8; ni++) {
        int col = ntile * BN + warpN * 64 + ni * 8 + qc * 2;
        float bs0 = g_b1p[col], bs1 = g_b1p[col + 1];
        #pragma unroll
        for (int mi = 0; mi < 2; mi++) {
            #pragma unroll
            for (int half = 0; half < 2; half++) {
                int m = mtile * BM + warpM * 32 + mi * 16 + qr + half * 8;
                if (m < MROWS) {
                    float v0 = gelu_exact(acc[mi][ni][half * 2 + 0] + bs0);
                    float v1 = gelu_exact(acc[mi][ni][half * 2 + 1] + bs1);
                    *(float2*)(g_h + (size_t)m * N1 + col) = make_float2(v0, v1);
                }
            }
        }
    }
}

// ============ kernel 2: out = h @ W2 + b2 ============
__global__ __launch_bounds__(256, 1)
void k2_gemm(const float* __restrict__ W2, const float* __restrict__ b2,
             float* __restrict__ out) {
    extern __shared__ float smem[];
    float* Abuf = smem;
    float* Bbuf = smem + STAGES * A_ELE;

    const int tid   = threadIdx.x;
    const int lane  = tid & 31;
    const int warp  = tid >> 5;
    const int warpM = warp & 3;
    const int warpN = warp >> 2;
    const int qr    = lane >> 2;
    const int qc    = lane & 3;
    const int mtile = blockIdx.x;

    const int arow  = tid >> 3;
    const int acol4 = tid & 7;
    int mrow[4];
    #pragma unroll
    for (int i = 0; i < 4; i++) {
        int m = mtile * BM + arow + i * 32;
        mrow[i] = (m < MROWS) ? m : (MROWS - 1);
    }
    const int bkrow = tid >> 5;
    const int bcol4 = tid & 31;

    const int NCHUNK = K2 / BK;   // 8

    auto load_chunk = [&](int kc) {
        int s = kc % STAGES;
        float* As = Abuf + s * A_ELE;
        float* Bs = Bbuf + s * B_ELE;
        #pragma unroll
        for (int i = 0; i < 4; i++) {
            const float* src = g_h + (size_t)mrow[i] * K2 + kc * BK + acol4 * 4;
            uint32_t dst = (uint32_t)__cvta_generic_to_shared(As + (arow + i * 32) * ASTR + acol4 * 4);
            cp_async16(dst, src);
        }
        #pragma unroll
        for (int i = 0; i < 4; i++) {
            int kr = bkrow + i * 8;
            const float* src = W2 + (size_t)(kc * BK + kr) * N2 + bcol4 * 4;
            uint32_t dst = (uint32_t)__cvta_generic_to_shared(Bs + kr * BSTR + bcol4 * 4);
            cp_async16(dst, src);
        }
    };

    float acc[2][8][4];
    #pragma unroll
    for (int a = 0; a < 2; a++)
        #pragma unroll
        for (int b = 0; b < 8; b++)
            #pragma unroll
            for (int c = 0; c < 4; c++) acc[a][b][c] = 0.f;

    #pragma unroll
    for (int c = 0; c < STAGES - 1; c++) { load_chunk(c); cp_commit(); }

    for (int kc = 0; kc < NCHUNK; kc++) {
        asm volatile("cp.async.wait_group %0;" :: "n"(STAGES - 2));
        __syncthreads();
        if (kc + STAGES - 1 < NCHUNK) load_chunk(kc + STAGES - 1);
        cp_commit();

        int s = kc % STAGES;
        const float* As = Abuf + s * A_ELE;
        const float* Bs = Bbuf + s * B_ELE;
        #pragma unroll
        for (int ks = 0; ks < 4; ks++) {
            uint32_t af[2][4];
            #pragma unroll
            for (int mi = 0; mi < 2; mi++) {
                int r0 = warpM * 32 + mi * 16 + qr;
                af[mi][0] = cvt_tf32(As[ r0      * ASTR + ks * 8 + qc    ]);
                af[mi][1] = cvt_tf32(As[(r0 + 8) * ASTR + ks * 8 + qc    ]);
                af[mi][2] = cvt_tf32(As[ r0      * ASTR + ks * 8 + qc + 4]);
                af[mi][3] = cvt_tf32(As[(r0 + 8) * ASTR + ks * 8 + qc + 4]);
            }
            #pragma unroll
            for (int ni = 0; ni < 8; ni++) {
                int c0 = warpN * 64 + ni * 8 + qr;
                uint32_t bf[2];
                bf[0] = cvt_tf32(Bs[(ks * 8 + qc    ) * BSTR + c0]);
                bf[1] = cvt_tf32(Bs[(ks * 8 + qc + 4) * BSTR + c0]);
                mma_tf32(acc[0][ni], af[0], bf);
                mma_tf32(acc[1][ni], af[1], bf);
            }
        }
    }

    // epilogue: + b2 -> out
    #pragma unroll
    for (int ni = 0; ni < 8; ni++) {
        int col = warpN * 64 + ni * 8 + qc * 2;
        float bs0 = b2[col], bs1 = b2[col + 1];
        #pragma unroll
        for (int mi = 0; mi < 2; mi++) {
            #pragma unroll
            for (int half = 0; half < 2; half++) {
                int m = mtile * BM + warpM * 32 + mi * 16 + qr + half * 8;
                if (m < MROWS) {
                    float v0 = acc[mi][ni][half * 2 + 0] + bs0;
                    float v1 = acc[mi][ni][half * 2 + 1] + bs1;
                    *(float2*)(out + (size_t)m * N2 + col) = make_float2(v0, v1);
                }
            }
        }
    }
}

// ---------------- launch ----------------
extern "C" void kernel_launch(void* const* d_in, const int* in_sizes, int n_in,
                              void* d_out, int out_size) {
    const float* x   = (const float*)d_in[0];
    const float* pos = (const float*)d_in[1];
    const float* W1  = (const float*)d_in[2];
    const float* b1  = (const float*)d_in[3];
    const float* W2  = (const float*)d_in[4];
    const float* b2  = (const float*)d_in[5];
    float* out = (float*)d_out;

    cudaFuncSetAttribute(k1_gemm_gelu, cudaFuncAttributeMaxDynamicSharedMemorySize, SMEM_BYTES);
    cudaFuncSetAttribute(k2_gemm,      cudaFuncAttributeMaxDynamicSharedMemorySize, SMEM_BYTES);

    // fold pos into bias: b1' = b1 + pos_flat @ W1
    pos_w1_partial<<<32, 256>>>(pos, W1);
    pos_w1_reduce<<<1, 256>>>(b1);

    dim3 g1((MROWS + BM - 1) / BM, N1 / BN);   // (64, 2)
    k1_gemm_gelu<<<g1, 256, SMEM_BYTES>>>(x, W1);

    dim3 g2((MROWS + BM - 1) / BM, 1);         // (64, 1)
    k2_gemm<<<g2, 256, SMEM_BYTES>>>(W2, b2, out);
}